// round 2
// baseline (speedup 1.0000x reference)
#include <cuda_runtime.h>
#include <math.h>

#define NLEV 16
#define P2 2654435761u
#define P3 805459861u

struct LevelParams {
    int          R[NLEV];
    unsigned int H[NLEV];
    int          O[NLEV];
    int          mode[NLEV];   // 0 = linear, 1 = hashed+dedup (R<=512), 2 = hashed direct
};

__device__ __forceinline__ unsigned long long pack2(float lo, float hi) {
    unsigned long long r;
    asm("mov.b64 %0, {%1, %2};" : "=l"(r) : "f"(lo), "f"(hi));
    return r;
}
__device__ __forceinline__ void unpack2(unsigned long long v, float &lo, float &hi) {
    asm("mov.b64 {%0, %1}, %2;" : "=f"(lo), "=f"(hi) : "l"(v));
}
// d += a * b, elementwise on packed f32x2 (exact fp32 semantics, 2 FMAs / issue slot)
__device__ __forceinline__ void ffma2(unsigned long long &d, unsigned long long a, unsigned long long b) {
    asm("fma.rn.f32x2 %0, %1, %2, %0;" : "+l"(d) : "l"(a), "l"(b));
}

__global__ void __launch_bounds__(256) grid_fused_kernel(
    const float* __restrict__ xyz,
    const float* __restrict__ bound,
    const float* __restrict__ table,
    const float* __restrict__ w1,
    const float* __restrict__ w2,
    float* __restrict__ out,
    LevelParams lev, int N)
{
    __shared__ __align__(16) float w1s[64][32];          // w1s[j][i] = w1[i][j]
    __shared__ __align__(16) float w2s[64][8];
    __shared__ unsigned long long ubuf[2][32 * 29];      // per-group 27-slot union, stride 29 (bank spread)

    const int tid = threadIdx.x;
    for (int i = tid; i < 64 * 32; i += 256) {
        int r = i >> 6, c = i & 63;                      // w1 is [32,64] row-major
        w1s[c][r] = w1[i];
    }
    for (int i = tid; i < 64 * 8; i += 256) {
        w2s[i >> 3][i & 7] = w2[i];
    }
    __syncthreads();

    int gt = blockIdx.x * 256 + tid;
    int p  = gt >> 3;
    int oc = gt & 7;          // lanes 0..7 of a group = the 8 outer corners of one point
    int g  = tid >> 3;        // group index within block (0..31)
    if (p >= N) return;

    const float b     = bound[0];
    const float inv2b = 1.0f / (2.0f * b);

    float cx = (xyz[3 * p + 0] + b) * inv2b * 512.0f;
    float cy = (xyz[3 * p + 1] + b) * inv2b * 512.0f;
    float cz = (xyz[3 * p + 2] + b) * inv2b * 512.0f;

    int c0x = min(max((int)floorf(cx), 0), 511);
    int c0y = min(max((int)floorf(cy), 0), 511);
    int c0z = min(max((int)floorf(cz), 0), 511);

    float u = cx - (float)c0x;
    float v = cy - (float)c0y;
    float w = cz - (float)c0z;

    // CORNERS order: index bit2 -> dim0(x), bit1 -> dim1(y), bit0 -> dim2(z)
    int ox = (oc >> 2) & 1, oy = (oc >> 1) & 1, oz = oc & 1;
    float wt = (ox ? u : 1.0f - u) * (oy ? v : 1.0f - v) * (oz ? w : 1.0f - w);

    // encode-point coordinates for o=0 and o=1 per dim (exact: integer/512)
    float e0x = (float)c0x * (1.0f / 512.0f), e1x = (float)(c0x + 1) * (1.0f / 512.0f);
    float e0y = (float)c0y * (1.0f / 512.0f), e1y = (float)(c0y + 1) * (1.0f / 512.0f);
    float e0z = (float)c0z * (1.0f / 512.0f), e1z = (float)(c0z + 1) * (1.0f / 512.0f);
    float ex = ox ? e1x : e0x;
    float ey = oy ? e1y : e0y;
    float ez = oz ? e1z : e0z;

    unsigned long long f2[NLEV];   // packed (feat0, feat1) per level
    int pb = 0;                    // union-buffer parity

    #pragma unroll
    for (int l = 0; l < NLEV; l++) {
        const float Rf = (float)lev.R[l];
        const unsigned H = lev.H[l];
        const unsigned long long* tab8 =
            reinterpret_cast<const unsigned long long*>(table) + lev.O[l];
        unsigned long long a = 0ull;

        if (lev.mode[l] == 1) {
            // ---- hashed level with 3x3x3 union dedup (R <= 512 -> per-dim delta in {0,1}) ----
            float px0 = e0x * Rf + 0.5f, px1 = e1x * Rf + 0.5f;
            float py0 = e0y * Rf + 0.5f, py1 = e1y * Rf + 0.5f;
            float pz0 = e0z * Rf + 0.5f, pz1 = e1z * Rf + 0.5f;
            float b0x = floorf(px0), b1x = floorf(px1);
            float b0y = floorf(py0), b1y = floorf(py1);
            float b0z = floorf(pz0), b1z = floorf(pz1);
            int dlx = (int)(b1x - b0x);
            int dly = (int)(b1y - b0y);
            int dlz = (int)(b1z - b0z);
            float fx = ox ? (px1 - b1x) : (px0 - b0x);
            float fy = oy ? (py1 - b1y) : (py0 - b0y);
            float fz = oz ? (pz1 - b1z) : (pz0 - b0z);

            unsigned mx = (unsigned)(int)b0x;
            unsigned uy = ((unsigned)(int)b0y) * P2;
            unsigned uz = ((unsigned)(int)b0z) * P3;
            unsigned mask = H - 1u;                     // H == 2^19 for hashed levels

            unsigned long long* bw = &ubuf[pb][g * 29];

            // cooperative union load: slots oc, oc+8, oc+16, oc+24
            #pragma unroll
            for (int k = 0; k < 4; k++) {
                int s = oc + k * 8;
                int sx = (s >= 18) ? 2 : ((s >= 9) ? 1 : 0);
                int rr = s - sx * 9;
                int sy = (rr >= 6) ? 2 : ((rr >= 3) ? 1 : 0);
                int sz = rr - sy * 3;
                bool valid = (s < 27) && (sx <= dlx + 1) && (sy <= dly + 1) && (sz <= dlz + 1);
                if (valid) {
                    unsigned idx = ((mx + (unsigned)sx)
                                  ^ (uy + (unsigned)sy * P2)
                                  ^ (uz + (unsigned)sz * P3)) & mask;
                    bw[s] = __ldg(tab8 + idx);
                }
            }
            __syncwarp(0xffffffffu);

            int base = (ox * dlx) * 9 + (oy * dly) * 3 + (oz * dlz);
            float wx0 = 1.0f - fx;
            float wy0 = 1.0f - fy, wz0 = 1.0f - fz;
            float wyz00 = wy0 * wz0, wyz01 = wy0 * fz, wyz10 = fy * wz0, wyz11 = fy * fz;

            #pragma unroll
            for (int dx = 0; dx < 2; dx++) {
                float wxd = dx ? fx : wx0;
                #pragma unroll
                for (int dy = 0; dy < 2; dy++) {
                    #pragma unroll
                    for (int dz = 0; dz < 2; dz++) {
                        unsigned long long t = bw[base + dx * 9 + dy * 3 + dz];
                        float wgt = wxd * (dy ? (dz ? wyz11 : wyz10)
                                              : (dz ? wyz01 : wyz00));
                        ffma2(a, pack2(wgt, wgt), t);
                    }
                }
            }
            pb ^= 1;
        } else {
            // ---- direct paths (linear levels, and hashed R=513) ----
            float px = ex * Rf + 0.5f;
            float py = ey * Rf + 0.5f;
            float pz = ez * Rf + 0.5f;
            float pgx = floorf(px), pgy = floorf(py), pgz = floorf(pz);
            float fx = px - pgx, fy = py - pgy, fz = pz - pgz;
            int ix = (int)pgx, iy = (int)pgy, iz = (int)pgz;

            float wx0 = 1.0f - fx;
            float wy0 = 1.0f - fy, wz0 = 1.0f - fz;
            float wyz00 = wy0 * wz0, wyz01 = wy0 * fz, wyz10 = fy * wz0, wyz11 = fy * fz;

            if (lev.mode[l] == 0) {
                int s1 = lev.R[l] + 1, s2 = s1 * s1;
                int base = ix + iy * s1 + iz * s2;
                #pragma unroll
                for (int dx = 0; dx < 2; dx++) {
                    float wxd = dx ? fx : wx0;
                    #pragma unroll
                    for (int dy = 0; dy < 2; dy++) {
                        #pragma unroll
                        for (int dz = 0; dz < 2; dz++) {
                            int idx = base + dx + dy * s1 + dz * s2;
                            if (idx >= (int)H) idx -= (int)H;   // idx < 2H provable
                            unsigned long long t = __ldg(tab8 + idx);
                            float wgt = wxd * (dy ? (dz ? wyz11 : wyz10)
                                                  : (dz ? wyz01 : wyz00));
                            ffma2(a, pack2(wgt, wgt), t);
                        }
                    }
                }
            } else {
                unsigned mask = H - 1u;
                unsigned hx0 = (unsigned)ix,        hx1 = hx0 + 1u;
                unsigned hy0 = (unsigned)iy * P2,   hy1 = hy0 + P2;
                unsigned hz0 = (unsigned)iz * P3,   hz1 = hz0 + P3;
                #pragma unroll
                for (int dx = 0; dx < 2; dx++) {
                    float wxd = dx ? fx : wx0;
                    unsigned hx = dx ? hx1 : hx0;
                    #pragma unroll
                    for (int dy = 0; dy < 2; dy++) {
                        unsigned hxy = hx ^ (dy ? hy1 : hy0);
                        #pragma unroll
                        for (int dz = 0; dz < 2; dz++) {
                            unsigned idx = (hxy ^ (dz ? hz1 : hz0)) & mask;
                            unsigned long long t = __ldg(tab8 + idx);
                            float wgt = wxd * (dy ? (dz ? wyz11 : wyz10)
                                                  : (dz ? wyz01 : wyz00));
                            ffma2(a, pack2(wgt, wgt), t);
                        }
                    }
                }
            }
        }
        f2[l] = a;
    }

    // ---- MLP: out = (relu(feats @ w1) @ w2) * wt   (packed f32x2) ----
    unsigned long long acc01 = 0ull, acc23 = 0ull, acc45 = 0ull, acc67 = 0ull;

    #pragma unroll 4
    for (int j = 0; j < 64; j++) {
        const ulonglong2* wr = reinterpret_cast<const ulonglong2*>(&w1s[j][0]);
        unsigned long long h0 = 0ull, h1 = 0ull;
        #pragma unroll
        for (int q = 0; q < 8; q++) {
            ulonglong2 wv = wr[q];
            ffma2(h0, f2[2 * q],     wv.x);
            ffma2(h1, f2[2 * q + 1], wv.y);
        }
        float h0lo, h0hi, h1lo, h1hi;
        unpack2(h0, h0lo, h0hi);
        unpack2(h1, h1lo, h1hi);
        float h = fmaxf((h0lo + h0hi) + (h1lo + h1hi), 0.0f) * wt;
        unsigned long long hh = pack2(h, h);
        const ulonglong2* w2r = reinterpret_cast<const ulonglong2*>(&w2s[j][0]);
        ulonglong2 wa = w2r[0];
        ulonglong2 wb = w2r[1];
        ffma2(acc01, hh, wa.x);
        ffma2(acc23, hh, wa.y);
        ffma2(acc45, hh, wb.x);
        ffma2(acc67, hh, wb.y);
    }

    float acc[8];
    unpack2(acc01, acc[0], acc[1]);
    unpack2(acc23, acc[2], acc[3]);
    unpack2(acc45, acc[4], acc[5]);
    unpack2(acc67, acc[6], acc[7]);

    // ---- reduce the 8 outer-corner contributions across the 8-lane group ----
    #pragma unroll
    for (int k = 0; k < 8; k++) {
        acc[k] += __shfl_xor_sync(0xffffffffu, acc[k], 1);
        acc[k] += __shfl_xor_sync(0xffffffffu, acc[k], 2);
        acc[k] += __shfl_xor_sync(0xffffffffu, acc[k], 4);
    }
    float t0 = (oc & 1) ? acc[1] : acc[0];
    float t1 = (oc & 1) ? acc[3] : acc[2];
    float t2 = (oc & 1) ? acc[5] : acc[4];
    float t3 = (oc & 1) ? acc[7] : acc[6];
    float u0 = (oc & 2) ? t1 : t0;
    float u1 = (oc & 2) ? t3 : t2;
    float vv = (oc & 4) ? u1 : u0;
    out[gt] = vv;
}

extern "C" void kernel_launch(void* const* d_in, const int* in_sizes, int n_in,
                              void* d_out, int out_size)
{
    const float* xyz   = (const float*)d_in[0];
    const float* bound = (const float*)d_in[1];
    const float* table = (const float*)d_in[2];
    const float* w1    = (const float*)d_in[3];
    const float* w2    = (const float*)d_in[4];
    float* out = (float*)d_out;

    int N = in_sizes[0] / 3;

    // Replicate torch-ngp level construction with the exact numpy double math.
    LevelParams lev;
    double scale = exp2(log2(513.0 / 16.0) / 15.0);
    long long off = 0;
    for (int i = 0; i < NLEV; i++) {
        int res = (int)ceil(16.0 * pow(scale, (double)i));
        long long cube = (long long)(res + 1) * (res + 1) * (res + 1);
        long long n = cube;
        if (n > (1LL << 19)) n = (1LL << 19);
        n = ((n + 7) / 8) * 8;
        lev.R[i] = res;
        lev.H[i] = (unsigned)n;
        lev.O[i] = (int)off;
        int linear = (cube <= n) ? 1 : 0;
        lev.mode[i] = linear ? 0 : ((res <= 512) ? 1 : 2);
        off += n;
    }

    int total_threads = N * 8;
    int blocks = (total_threads + 255) / 256;
    grid_fused_kernel<<<blocks, 256>>>(xyz, bound, table, w1, w2, out, lev, N);
}

// round 3
// speedup vs baseline: 1.1644x; 1.1644x over previous
#include <cuda_runtime.h>
#include <math.h>

#define NLEV 16
#define P2 2654435761u
#define P3 805459861u

struct LevelParams {
    int          R[NLEV];
    unsigned int H[NLEV];
    int          O[NLEV];
    int          linear[NLEV];
};

__device__ __forceinline__ unsigned long long pack2(float lo, float hi) {
    unsigned long long r;
    asm("mov.b64 %0, {%1, %2};" : "=l"(r) : "f"(lo), "f"(hi));
    return r;
}
__device__ __forceinline__ void unpack2(unsigned long long v, float &lo, float &hi) {
    asm("mov.b64 {%0, %1}, %2;" : "=f"(lo), "=f"(hi) : "l"(v));
}
// d += a * b elementwise on packed f32x2 (exact fp32 semantics, 2 FMAs / slot)
__device__ __forceinline__ void ffma2(unsigned long long &d, unsigned long long a, unsigned long long b) {
    asm("fma.rn.f32x2 %0, %1, %2, %0;" : "+l"(d) : "l"(a), "l"(b));
}

// Direct (round-1 proven) multires hash-grid encode for one encode-point.
__device__ __forceinline__ void encode_point(
    const LevelParams& lev, const float* __restrict__ table,
    float ex, float ey, float ez, unsigned long long* __restrict__ f2)
{
    #pragma unroll
    for (int l = 0; l < NLEV; l++) {
        const float Rf = (float)lev.R[l];
        const unsigned H = lev.H[l];
        const unsigned long long* tab8 =
            reinterpret_cast<const unsigned long long*>(table) + lev.O[l];

        float px = ex * Rf + 0.5f;   // ex*R exact (k*R < 2^24) -> rounding-free
        float py = ey * Rf + 0.5f;
        float pz = ez * Rf + 0.5f;
        float pgx = floorf(px), pgy = floorf(py), pgz = floorf(pz);
        float fx = px - pgx, fy = py - pgy, fz = pz - pgz;
        int ix = (int)pgx, iy = (int)pgy, iz = (int)pgz;

        float wx0 = 1.0f - fx;
        float wy0 = 1.0f - fy, wz0 = 1.0f - fz;
        float wyz00 = wy0 * wz0, wyz01 = wy0 * fz, wyz10 = fy * wz0, wyz11 = fy * fz;

        unsigned long long a = 0ull;

        if (lev.linear[l]) {
            int s1 = lev.R[l] + 1, s2 = s1 * s1;
            int base = ix + iy * s1 + iz * s2;
            #pragma unroll
            for (int dx = 0; dx < 2; dx++) {
                float wxd = dx ? fx : wx0;
                #pragma unroll
                for (int dy = 0; dy < 2; dy++) {
                    #pragma unroll
                    for (int dz = 0; dz < 2; dz++) {
                        int idx = base + dx + dy * s1 + dz * s2;
                        if (idx >= (int)H) idx -= (int)H;   // idx < 2H provable
                        unsigned long long t = __ldg(tab8 + idx);
                        float wgt = wxd * (dy ? (dz ? wyz11 : wyz10)
                                              : (dz ? wyz01 : wyz00));
                        ffma2(a, pack2(wgt, wgt), t);
                    }
                }
            }
        } else {
            unsigned mask = H - 1u;                 // H == 2^19 for hashed levels
            unsigned hx0 = (unsigned)ix,        hx1 = hx0 + 1u;
            unsigned hy0 = (unsigned)iy * P2,   hy1 = hy0 + P2;
            unsigned hz0 = (unsigned)iz * P3,   hz1 = hz0 + P3;
            #pragma unroll
            for (int dx = 0; dx < 2; dx++) {
                float wxd = dx ? fx : wx0;
                unsigned hx = dx ? hx1 : hx0;
                #pragma unroll
                for (int dy = 0; dy < 2; dy++) {
                    unsigned hxy = hx ^ (dy ? hy1 : hy0);
                    #pragma unroll
                    for (int dz = 0; dz < 2; dz++) {
                        unsigned idx = (hxy ^ (dz ? hz1 : hz0)) & mask;
                        unsigned long long t = __ldg(tab8 + idx);
                        float wgt = wxd * (dy ? (dz ? wyz11 : wyz10)
                                              : (dz ? wyz01 : wyz00));
                        ffma2(a, pack2(wgt, wgt), t);
                    }
                }
            }
        }
        f2[l] = a;
    }
}

// Computes (ex,ey,ez, wt) for item (point p, outer corner oc).
__device__ __forceinline__ void setup_item(
    const float* __restrict__ xyz, float b, float inv2b, int p, int oc,
    float& ex, float& ey, float& ez, float& wt)
{
    float cx = (xyz[3 * p + 0] + b) * inv2b * 512.0f;
    float cy = (xyz[3 * p + 1] + b) * inv2b * 512.0f;
    float cz = (xyz[3 * p + 2] + b) * inv2b * 512.0f;

    int c0x = min(max((int)floorf(cx), 0), 511);
    int c0y = min(max((int)floorf(cy), 0), 511);
    int c0z = min(max((int)floorf(cz), 0), 511);

    float u = cx - (float)c0x;
    float v = cy - (float)c0y;
    float w = cz - (float)c0z;

    int ox = (oc >> 2) & 1, oy = (oc >> 1) & 1, oz = oc & 1;
    wt = (ox ? u : 1.0f - u) * (oy ? v : 1.0f - v) * (oz ? w : 1.0f - w);

    ex = (float)(c0x + ox) * (1.0f / 512.0f);
    ey = (float)(c0y + oy) * (1.0f / 512.0f);
    ez = (float)(c0z + oz) * (1.0f / 512.0f);
}

__global__ void __launch_bounds__(128, 2) grid_fused_kernel(
    const float* __restrict__ xyz,
    const float* __restrict__ bound,
    const float* __restrict__ table,
    const float* __restrict__ w1,
    const float* __restrict__ w2,
    float* __restrict__ out,
    LevelParams lev, int N)
{
    __shared__ __align__(16) float w1s[64][32];  // w1s[j][i] = w1[i][j]
    __shared__ __align__(16) float w2s[64][8];

    const int tid = threadIdx.x;
    for (int i = tid; i < 64 * 32; i += 128) {
        int r = i >> 6, c = i & 63;              // w1 is [32,64] row-major
        w1s[c][r] = w1[i];
    }
    for (int i = tid; i < 64 * 8; i += 128) {
        w2s[i >> 3][i & 7] = w2[i];
    }
    __syncthreads();

    const int M     = N * 8;                     // total (point, corner) items
    const int half  = M >> 1;
    int T = blockIdx.x * 128 + tid;              // thread handles items T and T+half
    if (T >= half) return;

    int gtA = T;
    int gtB = T + half;
    int pA  = gtA >> 3;
    int pB  = gtB >> 3;
    int oc  = gtA & 7;    // same for both items (half is a multiple of 8)

    const float b     = bound[0];
    const float inv2b = 1.0f / (2.0f * b);

    float exA, eyA, ezA, wtA;
    float exB, eyB, ezB, wtB;
    setup_item(xyz, b, inv2b, pA, oc, exA, eyA, ezA, wtA);
    setup_item(xyz, b, inv2b, pB, oc, exB, eyB, ezB, wtB);

    unsigned long long fA[NLEV], fB[NLEV];
    encode_point(lev, table, exA, eyA, ezA, fA);
    encode_point(lev, table, exB, eyB, ezB, fB);

    // ---- fused MLP for both items: each weight load feeds 2 items ----
    unsigned long long accA01 = 0ull, accA23 = 0ull, accA45 = 0ull, accA67 = 0ull;
    unsigned long long accB01 = 0ull, accB23 = 0ull, accB45 = 0ull, accB67 = 0ull;

    #pragma unroll 2
    for (int j = 0; j < 64; j++) {
        const ulonglong2* wr = reinterpret_cast<const ulonglong2*>(&w1s[j][0]);
        unsigned long long hA0 = 0ull, hA1 = 0ull, hB0 = 0ull, hB1 = 0ull;
        #pragma unroll
        for (int q = 0; q < 8; q++) {
            ulonglong2 wv = wr[q];
            ffma2(hA0, fA[2 * q],     wv.x);
            ffma2(hA1, fA[2 * q + 1], wv.y);
            ffma2(hB0, fB[2 * q],     wv.x);
            ffma2(hB1, fB[2 * q + 1], wv.y);
        }
        float a0, a1, a2, a3, b0, b1, b2, b3;
        unpack2(hA0, a0, a1); unpack2(hA1, a2, a3);
        unpack2(hB0, b0, b1); unpack2(hB1, b2, b3);
        float hA = fmaxf((a0 + a1) + (a2 + a3), 0.0f) * wtA;
        float hB = fmaxf((b0 + b1) + (b2 + b3), 0.0f) * wtB;
        unsigned long long hhA = pack2(hA, hA);
        unsigned long long hhB = pack2(hB, hB);

        const ulonglong2* w2r = reinterpret_cast<const ulonglong2*>(&w2s[j][0]);
        ulonglong2 wa = w2r[0];
        ulonglong2 wb = w2r[1];
        ffma2(accA01, hhA, wa.x); ffma2(accA23, hhA, wa.y);
        ffma2(accA45, hhA, wb.x); ffma2(accA67, hhA, wb.y);
        ffma2(accB01, hhB, wa.x); ffma2(accB23, hhB, wa.y);
        ffma2(accB45, hhB, wb.x); ffma2(accB67, hhB, wb.y);
    }

    float accA[8], accB[8];
    unpack2(accA01, accA[0], accA[1]); unpack2(accA23, accA[2], accA[3]);
    unpack2(accA45, accA[4], accA[5]); unpack2(accA67, accA[6], accA[7]);
    unpack2(accB01, accB[0], accB[1]); unpack2(accB23, accB[2], accB[3]);
    unpack2(accB45, accB[4], accB[5]); unpack2(accB67, accB[6], accB[7]);

    // ---- reduce the 8 outer-corner contributions across the 8-lane group ----
    #pragma unroll
    for (int k = 0; k < 8; k++) {
        accA[k] += __shfl_xor_sync(0xffffffffu, accA[k], 1);
        accA[k] += __shfl_xor_sync(0xffffffffu, accA[k], 2);
        accA[k] += __shfl_xor_sync(0xffffffffu, accA[k], 4);
        accB[k] += __shfl_xor_sync(0xffffffffu, accB[k], 1);
        accB[k] += __shfl_xor_sync(0xffffffffu, accB[k], 2);
        accB[k] += __shfl_xor_sync(0xffffffffu, accB[k], 4);
    }
    // lane oc writes output element oc of its point -> coalesced stores
    float tA0 = (oc & 1) ? accA[1] : accA[0];
    float tA1 = (oc & 1) ? accA[3] : accA[2];
    float tA2 = (oc & 1) ? accA[5] : accA[4];
    float tA3 = (oc & 1) ? accA[7] : accA[6];
    float uA0 = (oc & 2) ? tA1 : tA0;
    float uA1 = (oc & 2) ? tA3 : tA2;
    out[gtA] = (oc & 4) ? uA1 : uA0;

    float tB0 = (oc & 1) ? accB[1] : accB[0];
    float tB1 = (oc & 1) ? accB[3] : accB[2];
    float tB2 = (oc & 1) ? accB[5] : accB[4];
    float tB3 = (oc & 1) ? accB[7] : accB[6];
    float uB0 = (oc & 2) ? tB1 : tB0;
    float uB1 = (oc & 2) ? tB3 : tB2;
    out[gtB] = (oc & 4) ? uB1 : uB0;
}

extern "C" void kernel_launch(void* const* d_in, const int* in_sizes, int n_in,
                              void* d_out, int out_size)
{
    const float* xyz   = (const float*)d_in[0];
    const float* bound = (const float*)d_in[1];
    const float* table = (const float*)d_in[2];
    const float* w1    = (const float*)d_in[3];
    const float* w2    = (const float*)d_in[4];
    float* out = (float*)d_out;

    int N = in_sizes[0] / 3;

    // Replicate torch-ngp level construction with the exact numpy double math.
    LevelParams lev;
    double scale = exp2(log2(513.0 / 16.0) / 15.0);
    long long off = 0;
    for (int i = 0; i < NLEV; i++) {
        int res = (int)ceil(16.0 * pow(scale, (double)i));
        long long cube = (long long)(res + 1) * (res + 1) * (res + 1);
        long long n = cube;
        if (n > (1LL << 19)) n = (1LL << 19);
        n = ((n + 7) / 8) * 8;
        lev.R[i] = res;
        lev.H[i] = (unsigned)n;
        lev.O[i] = (int)off;
        lev.linear[i] = (cube <= n) ? 1 : 0;
        off += n;
    }

    int half = (N * 8) / 2;
    int blocks = (half + 127) / 128;
    grid_fused_kernel<<<blocks, 128>>>(xyz, bound, table, w1, w2, out, lev, N);
}

// round 4
// speedup vs baseline: 1.4111x; 1.2118x over previous
#include <cuda_runtime.h>
#include <math.h>

#define NLEV 16
#define P2 2654435761u
#define P3 805459861u

struct LevelParams {
    int          R[NLEV];
    unsigned int H[NLEV];
    int          O[NLEV];
    int          linear[NLEV];
};

__device__ __forceinline__ unsigned long long pack2(float lo, float hi) {
    unsigned long long r;
    asm("mov.b64 %0, {%1, %2};" : "=l"(r) : "f"(lo), "f"(hi));
    return r;
}
__device__ __forceinline__ void unpack2(unsigned long long v, float &lo, float &hi) {
    asm("mov.b64 {%0, %1}, %2;" : "=f"(lo), "=f"(hi) : "l"(v));
}
// d += a * b elementwise on packed f32x2 (exact fp32 semantics, 2 FMAs / slot)
__device__ __forceinline__ void ffma2(unsigned long long &d, unsigned long long a, unsigned long long b) {
    asm("fma.rn.f32x2 %0, %1, %2, %0;" : "+l"(d) : "l"(a), "l"(b));
}

// Computes (ex,ey,ez, wt) for item (point p, outer corner oc).
__device__ __forceinline__ void setup_item(
    const float* __restrict__ xyz, float b, float inv2b, int p, int oc,
    float& ex, float& ey, float& ez, float& wt)
{
    float cx = (xyz[3 * p + 0] + b) * inv2b * 512.0f;
    float cy = (xyz[3 * p + 1] + b) * inv2b * 512.0f;
    float cz = (xyz[3 * p + 2] + b) * inv2b * 512.0f;

    int c0x = min(max((int)floorf(cx), 0), 511);
    int c0y = min(max((int)floorf(cy), 0), 511);
    int c0z = min(max((int)floorf(cz), 0), 511);

    float u = cx - (float)c0x;
    float v = cy - (float)c0y;
    float w = cz - (float)c0z;

    int ox = (oc >> 2) & 1, oy = (oc >> 1) & 1, oz = oc & 1;
    wt = (ox ? u : 1.0f - u) * (oy ? v : 1.0f - v) * (oz ? w : 1.0f - w);

    ex = (float)(c0x + ox) * (1.0f / 512.0f);
    ey = (float)(c0y + oy) * (1.0f / 512.0f);
    ez = (float)(c0z + oz) * (1.0f / 512.0f);
}

// Per-level interp weights + integer cell for one encode-point.
struct LevWts {
    float wx0, fx;
    float wyz00, wyz01, wyz10, wyz11;
    int ix, iy, iz;
};

__device__ __forceinline__ LevWts level_setup(float Rf, float ex, float ey, float ez) {
    LevWts s;
    float px = ex * Rf + 0.5f;   // ex*R exact (k*R < 2^24) -> rounding-free
    float py = ey * Rf + 0.5f;
    float pz = ez * Rf + 0.5f;
    float pgx = floorf(px), pgy = floorf(py), pgz = floorf(pz);
    float fx = px - pgx, fy = py - pgy, fz = pz - pgz;
    s.ix = (int)pgx; s.iy = (int)pgy; s.iz = (int)pgz;
    s.fx = fx; s.wx0 = 1.0f - fx;
    float wy0 = 1.0f - fy, wz0 = 1.0f - fz;
    s.wyz00 = wy0 * wz0; s.wyz01 = wy0 * fz; s.wyz10 = fy * wz0; s.wyz11 = fy * fz;
    return s;
}

__global__ void __launch_bounds__(128, 4) grid_fused_kernel(
    const float* __restrict__ xyz,
    const float* __restrict__ bound,
    const float* __restrict__ table,
    const float* __restrict__ w1,
    const float* __restrict__ w2,
    float* __restrict__ out,
    LevelParams lev, int N)
{
    __shared__ __align__(16) float w1s[64][32];  // w1s[j][i] = w1[i][j]
    __shared__ __align__(16) float w2s[64][8];

    const int tid = threadIdx.x;
    for (int i = tid; i < 64 * 32; i += 128) {
        int r = i >> 6, c = i & 63;              // w1 is [32,64] row-major
        w1s[c][r] = w1[i];
    }
    for (int i = tid; i < 64 * 8; i += 128) {
        w2s[i >> 3][i & 7] = w2[i];
    }
    __syncthreads();

    const int M     = N * 8;                     // total (point, corner) items
    const int half  = M >> 1;
    int T = blockIdx.x * 128 + tid;              // thread handles items T and T+half
    if (T >= half) return;

    int gtA = T;
    int gtB = T + half;
    int pA  = gtA >> 3;
    int pB  = gtB >> 3;
    int oc  = gtA & 7;    // same for both items (half is a multiple of 8)

    const float b     = bound[0];
    const float inv2b = 1.0f / (2.0f * b);

    float exA, eyA, ezA, wtA;
    float exB, eyB, ezB, wtB;
    setup_item(xyz, b, inv2b, pA, oc, exA, eyA, ezA, wtA);
    setup_item(xyz, b, inv2b, pB, oc, exB, eyB, ezB, wtB);

    unsigned long long fA[NLEV], fB[NLEV];

    // ---- interleaved encode: both items per level -> 16 independent gathers in flight ----
    #pragma unroll
    for (int l = 0; l < NLEV; l++) {
        const float Rf = (float)lev.R[l];
        const unsigned H = lev.H[l];
        const unsigned long long* tab8 =
            reinterpret_cast<const unsigned long long*>(table) + lev.O[l];

        LevWts A = level_setup(Rf, exA, eyA, ezA);
        LevWts B = level_setup(Rf, exB, eyB, ezB);

        unsigned long long aA = 0ull, aB = 0ull;

        if (lev.linear[l]) {
            int s1 = lev.R[l] + 1, s2 = s1 * s1;
            int baseA = A.ix + A.iy * s1 + A.iz * s2;
            int baseB = B.ix + B.iy * s1 + B.iz * s2;
            #pragma unroll
            for (int dx = 0; dx < 2; dx++) {
                float wxdA = dx ? A.fx : A.wx0;
                float wxdB = dx ? B.fx : B.wx0;
                #pragma unroll
                for (int dy = 0; dy < 2; dy++) {
                    #pragma unroll
                    for (int dz = 0; dz < 2; dz++) {
                        int idxA = baseA + dx + dy * s1 + dz * s2;
                        int idxB = baseB + dx + dy * s1 + dz * s2;
                        if (idxA >= (int)H) idxA -= (int)H;   // idx < 2H provable
                        if (idxB >= (int)H) idxB -= (int)H;
                        unsigned long long tA = __ldg(tab8 + idxA);
                        unsigned long long tB = __ldg(tab8 + idxB);
                        float wA = wxdA * (dy ? (dz ? A.wyz11 : A.wyz10)
                                              : (dz ? A.wyz01 : A.wyz00));
                        float wB = wxdB * (dy ? (dz ? B.wyz11 : B.wyz10)
                                              : (dz ? B.wyz01 : B.wyz00));
                        ffma2(aA, pack2(wA, wA), tA);
                        ffma2(aB, pack2(wB, wB), tB);
                    }
                }
            }
        } else {
            unsigned mask = H - 1u;                 // H == 2^19 for hashed levels
            unsigned hxA0 = (unsigned)A.ix,      hxA1 = hxA0 + 1u;
            unsigned hyA0 = (unsigned)A.iy * P2, hyA1 = hyA0 + P2;
            unsigned hzA0 = (unsigned)A.iz * P3, hzA1 = hzA0 + P3;
            unsigned hxB0 = (unsigned)B.ix,      hxB1 = hxB0 + 1u;
            unsigned hyB0 = (unsigned)B.iy * P2, hyB1 = hyB0 + P2;
            unsigned hzB0 = (unsigned)B.iz * P3, hzB1 = hzB0 + P3;
            #pragma unroll
            for (int dx = 0; dx < 2; dx++) {
                float wxdA = dx ? A.fx : A.wx0;
                float wxdB = dx ? B.fx : B.wx0;
                unsigned hxA = dx ? hxA1 : hxA0;
                unsigned hxB = dx ? hxB1 : hxB0;
                #pragma unroll
                for (int dy = 0; dy < 2; dy++) {
                    unsigned hxyA = hxA ^ (dy ? hyA1 : hyA0);
                    unsigned hxyB = hxB ^ (dy ? hyB1 : hyB0);
                    #pragma unroll
                    for (int dz = 0; dz < 2; dz++) {
                        unsigned idxA = (hxyA ^ (dz ? hzA1 : hzA0)) & mask;
                        unsigned idxB = (hxyB ^ (dz ? hzB1 : hzB0)) & mask;
                        unsigned long long tA = __ldg(tab8 + idxA);
                        unsigned long long tB = __ldg(tab8 + idxB);
                        float wA = wxdA * (dy ? (dz ? A.wyz11 : A.wyz10)
                                              : (dz ? A.wyz01 : A.wyz00));
                        float wB = wxdB * (dy ? (dz ? B.wyz11 : B.wyz10)
                                              : (dz ? B.wyz01 : B.wyz00));
                        ffma2(aA, pack2(wA, wA), tA);
                        ffma2(aB, pack2(wB, wB), tB);
                    }
                }
            }
        }
        fA[l] = aA;
        fB[l] = aB;
    }

    // ---- fused MLP for both items: each weight load feeds 2 items ----
    unsigned long long accA01 = 0ull, accA23 = 0ull, accA45 = 0ull, accA67 = 0ull;
    unsigned long long accB01 = 0ull, accB23 = 0ull, accB45 = 0ull, accB67 = 0ull;

    #pragma unroll 2
    for (int j = 0; j < 64; j++) {
        const ulonglong2* wr = reinterpret_cast<const ulonglong2*>(&w1s[j][0]);
        unsigned long long hA0 = 0ull, hA1 = 0ull, hB0 = 0ull, hB1 = 0ull;
        #pragma unroll
        for (int q = 0; q < 8; q++) {
            ulonglong2 wv = wr[q];
            ffma2(hA0, fA[2 * q],     wv.x);
            ffma2(hA1, fA[2 * q + 1], wv.y);
            ffma2(hB0, fB[2 * q],     wv.x);
            ffma2(hB1, fB[2 * q + 1], wv.y);
        }
        float a0, a1, a2, a3, b0, b1, b2, b3;
        unpack2(hA0, a0, a1); unpack2(hA1, a2, a3);
        unpack2(hB0, b0, b1); unpack2(hB1, b2, b3);
        float hA = fmaxf((a0 + a1) + (a2 + a3), 0.0f) * wtA;
        float hB = fmaxf((b0 + b1) + (b2 + b3), 0.0f) * wtB;
        unsigned long long hhA = pack2(hA, hA);
        unsigned long long hhB = pack2(hB, hB);

        const ulonglong2* w2r = reinterpret_cast<const ulonglong2*>(&w2s[j][0]);
        ulonglong2 wa = w2r[0];
        ulonglong2 wb = w2r[1];
        ffma2(accA01, hhA, wa.x); ffma2(accA23, hhA, wa.y);
        ffma2(accA45, hhA, wb.x); ffma2(accA67, hhA, wb.y);
        ffma2(accB01, hhB, wa.x); ffma2(accB23, hhB, wa.y);
        ffma2(accB45, hhB, wb.x); ffma2(accB67, hhB, wb.y);
    }

    float accA[8], accB[8];
    unpack2(accA01, accA[0], accA[1]); unpack2(accA23, accA[2], accA[3]);
    unpack2(accA45, accA[4], accA[5]); unpack2(accA67, accA[6], accA[7]);
    unpack2(accB01, accB[0], accB[1]); unpack2(accB23, accB[2], accB[3]);
    unpack2(accB45, accB[4], accB[5]); unpack2(accB67, accB[6], accB[7]);

    // ---- reduce the 8 outer-corner contributions across the 8-lane group ----
    #pragma unroll
    for (int k = 0; k < 8; k++) {
        accA[k] += __shfl_xor_sync(0xffffffffu, accA[k], 1);
        accA[k] += __shfl_xor_sync(0xffffffffu, accA[k], 2);
        accA[k] += __shfl_xor_sync(0xffffffffu, accA[k], 4);
        accB[k] += __shfl_xor_sync(0xffffffffu, accB[k], 1);
        accB[k] += __shfl_xor_sync(0xffffffffu, accB[k], 2);
        accB[k] += __shfl_xor_sync(0xffffffffu, accB[k], 4);
    }
    // lane oc writes output element oc of its point -> coalesced stores
    float tA0 = (oc & 1) ? accA[1] : accA[0];
    float tA1 = (oc & 1) ? accA[3] : accA[2];
    float tA2 = (oc & 1) ? accA[5] : accA[4];
    float tA3 = (oc & 1) ? accA[7] : accA[6];
    float uA0 = (oc & 2) ? tA1 : tA0;
    float uA1 = (oc & 2) ? tA3 : tA2;
    out[gtA] = (oc & 4) ? uA1 : uA0;

    float tB0 = (oc & 1) ? accB[1] : accB[0];
    float tB1 = (oc & 1) ? accB[3] : accB[2];
    float tB2 = (oc & 1) ? accB[5] : accB[4];
    float tB3 = (oc & 1) ? accB[7] : accB[6];
    float uB0 = (oc & 2) ? tB1 : tB0;
    float uB1 = (oc & 2) ? tB3 : tB2;
    out[gtB] = (oc & 4) ? uB1 : uB0;
}

extern "C" void kernel_launch(void* const* d_in, const int* in_sizes, int n_in,
                              void* d_out, int out_size)
{
    const float* xyz   = (const float*)d_in[0];
    const float* bound = (const float*)d_in[1];
    const float* table = (const float*)d_in[2];
    const float* w1    = (const float*)d_in[3];
    const float* w2    = (const float*)d_in[4];
    float* out = (float*)d_out;

    int N = in_sizes[0] / 3;

    // Replicate torch-ngp level construction with the exact numpy double math.
    LevelParams lev;
    double scale = exp2(log2(513.0 / 16.0) / 15.0);
    long long off = 0;
    for (int i = 0; i < NLEV; i++) {
        int res = (int)ceil(16.0 * pow(scale, (double)i));
        long long cube = (long long)(res + 1) * (res + 1) * (res + 1);
        long long n = cube;
        if (n > (1LL << 19)) n = (1LL << 19);
        n = ((n + 7) / 8) * 8;
        lev.R[i] = res;
        lev.H[i] = (unsigned)n;
        lev.O[i] = (int)off;
        lev.linear[i] = (cube <= n) ? 1 : 0;
        off += n;
    }

    int half = (N * 8) / 2;
    int blocks = (half + 127) / 128;
    grid_fused_kernel<<<blocks, 128>>>(xyz, bound, table, w1, w2, out, lev, N);
}

// round 5
// speedup vs baseline: 1.4917x; 1.0572x over previous
#include <cuda_runtime.h>
#include <math.h>

#define NLEV 16
#define P2 2654435761u
#define P3 805459861u

struct LevelParams {
    int          R[NLEV];
    unsigned int H[NLEV];
    int          O[NLEV];
    int          linear[NLEV];
};

// w1 transposed into constant memory: c_w1t[j*8+q] holds the 16B
// {w1[4q][j], w1[4q+1][j], w1[4q+2][j], w1[4q+3][j]} for hidden unit j.
__constant__ __align__(16) ulonglong2 c_w1t[512];
__device__   __align__(16) float      g_w1t[2048];   // transpose scratch

__device__ __forceinline__ unsigned long long pack2(float lo, float hi) {
    unsigned long long r;
    asm("mov.b64 %0, {%1, %2};" : "=l"(r) : "f"(lo), "f"(hi));
    return r;
}
__device__ __forceinline__ void unpack2(unsigned long long v, float &lo, float &hi) {
    asm("mov.b64 {%0, %1}, %2;" : "=f"(lo), "=f"(hi) : "l"(v));
}
// d += a * b elementwise on packed f32x2 (exact fp32 semantics, 2 FMAs / slot)
__device__ __forceinline__ void ffma2(unsigned long long &d, unsigned long long a, unsigned long long b) {
    asm("fma.rn.f32x2 %0, %1, %2, %0;" : "+l"(d) : "l"(a), "l"(b));
}

__global__ void transpose_w1_kernel(const float* __restrict__ w1) {
    int i = blockIdx.x * 256 + threadIdx.x;      // i over 2048 entries
    if (i < 2048) {
        int j = i >> 5;          // hidden unit 0..63
        int r = i & 31;          // input 0..31
        g_w1t[j * 32 + r] = w1[r * 64 + j];      // w1 is [32,64] row-major
    }
}

// Computes (ex,ey,ez, wt) for item (point p, outer corner oc).
__device__ __forceinline__ void setup_item(
    const float* __restrict__ xyz, float b, float inv2b, int p, int oc,
    float& ex, float& ey, float& ez, float& wt)
{
    float cx = (xyz[3 * p + 0] + b) * inv2b * 512.0f;
    float cy = (xyz[3 * p + 1] + b) * inv2b * 512.0f;
    float cz = (xyz[3 * p + 2] + b) * inv2b * 512.0f;

    int c0x = min(max((int)floorf(cx), 0), 511);
    int c0y = min(max((int)floorf(cy), 0), 511);
    int c0z = min(max((int)floorf(cz), 0), 511);

    float u = cx - (float)c0x;
    float v = cy - (float)c0y;
    float w = cz - (float)c0z;

    int ox = (oc >> 2) & 1, oy = (oc >> 1) & 1, oz = oc & 1;
    wt = (ox ? u : 1.0f - u) * (oy ? v : 1.0f - v) * (oz ? w : 1.0f - w);

    ex = (float)(c0x + ox) * (1.0f / 512.0f);
    ey = (float)(c0y + oy) * (1.0f / 512.0f);
    ez = (float)(c0z + oz) * (1.0f / 512.0f);
}

// Per-level interp weights + integer cell for one encode-point.
struct LevWts {
    float wx0, fx;
    float wyz00, wyz01, wyz10, wyz11;
    int ix, iy, iz;
};

__device__ __forceinline__ LevWts level_setup(float Rf, float ex, float ey, float ez) {
    LevWts s;
    float px = ex * Rf + 0.5f;   // ex*R exact (k*R < 2^24) -> rounding-free
    float py = ey * Rf + 0.5f;
    float pz = ez * Rf + 0.5f;
    float pgx = floorf(px), pgy = floorf(py), pgz = floorf(pz);
    float fx = px - pgx, fy = py - pgy, fz = pz - pgz;
    s.ix = (int)pgx; s.iy = (int)pgy; s.iz = (int)pgz;
    s.fx = fx; s.wx0 = 1.0f - fx;
    float wy0 = 1.0f - fy, wz0 = 1.0f - fz;
    s.wyz00 = wy0 * wz0; s.wyz01 = wy0 * fz; s.wyz10 = fy * wz0; s.wyz11 = fy * fz;
    return s;
}

__global__ void __launch_bounds__(128, 4) grid_fused_kernel(
    const float* __restrict__ xyz,
    const float* __restrict__ bound,
    const float* __restrict__ table,
    const float* __restrict__ w2,
    float* __restrict__ out,
    LevelParams lev, int N)
{
    __shared__ __align__(16) float w2s[64][8];

    const int tid = threadIdx.x;
    for (int i = tid; i < 64 * 8; i += 128) {
        w2s[i >> 3][i & 7] = w2[i];
    }
    __syncthreads();

    const int M     = N * 8;                     // total (point, corner) items
    const int half  = M >> 1;
    int T = blockIdx.x * 128 + tid;              // thread handles items T and T+half
    if (T >= half) return;

    int gtA = T;
    int gtB = T + half;
    int pA  = gtA >> 3;
    int pB  = gtB >> 3;
    int oc  = gtA & 7;    // same for both items (half is a multiple of 8)

    const float b     = bound[0];
    const float inv2b = 1.0f / (2.0f * b);

    float exA, eyA, ezA, wtA;
    float exB, eyB, ezB, wtB;
    setup_item(xyz, b, inv2b, pA, oc, exA, eyA, ezA, wtA);
    setup_item(xyz, b, inv2b, pB, oc, exB, eyB, ezB, wtB);

    unsigned long long fA[NLEV], fB[NLEV];

    // ---- interleaved encode: both items per level -> 16 independent gathers in flight ----
    #pragma unroll
    for (int l = 0; l < NLEV; l++) {
        const float Rf = (float)lev.R[l];
        const unsigned H = lev.H[l];
        const unsigned long long* tab8 =
            reinterpret_cast<const unsigned long long*>(table) + lev.O[l];

        LevWts A = level_setup(Rf, exA, eyA, ezA);
        LevWts B = level_setup(Rf, exB, eyB, ezB);

        unsigned long long aA = 0ull, aB = 0ull;

        if (lev.linear[l]) {
            int s1 = lev.R[l] + 1, s2 = s1 * s1;
            int baseA = A.ix + A.iy * s1 + A.iz * s2;
            int baseB = B.ix + B.iy * s1 + B.iz * s2;
            #pragma unroll
            for (int dx = 0; dx < 2; dx++) {
                float wxdA = dx ? A.fx : A.wx0;
                float wxdB = dx ? B.fx : B.wx0;
                #pragma unroll
                for (int dy = 0; dy < 2; dy++) {
                    #pragma unroll
                    for (int dz = 0; dz < 2; dz++) {
                        int idxA = baseA + dx + dy * s1 + dz * s2;
                        int idxB = baseB + dx + dy * s1 + dz * s2;
                        if (idxA >= (int)H) idxA -= (int)H;   // idx < 2H provable
                        if (idxB >= (int)H) idxB -= (int)H;
                        unsigned long long tA = __ldg(tab8 + idxA);
                        unsigned long long tB = __ldg(tab8 + idxB);
                        float wA = wxdA * (dy ? (dz ? A.wyz11 : A.wyz10)
                                              : (dz ? A.wyz01 : A.wyz00));
                        float wB = wxdB * (dy ? (dz ? B.wyz11 : B.wyz10)
                                              : (dz ? B.wyz01 : B.wyz00));
                        ffma2(aA, pack2(wA, wA), tA);
                        ffma2(aB, pack2(wB, wB), tB);
                    }
                }
            }
        } else {
            unsigned mask = H - 1u;                 // H == 2^19 for hashed levels
            unsigned hxA0 = (unsigned)A.ix,      hxA1 = hxA0 + 1u;
            unsigned hyA0 = (unsigned)A.iy * P2, hyA1 = hyA0 + P2;
            unsigned hzA0 = (unsigned)A.iz * P3, hzA1 = hzA0 + P3;
            unsigned hxB0 = (unsigned)B.ix,      hxB1 = hxB0 + 1u;
            unsigned hyB0 = (unsigned)B.iy * P2, hyB1 = hyB0 + P2;
            unsigned hzB0 = (unsigned)B.iz * P3, hzB1 = hzB0 + P3;
            #pragma unroll
            for (int dx = 0; dx < 2; dx++) {
                float wxdA = dx ? A.fx : A.wx0;
                float wxdB = dx ? B.fx : B.wx0;
                unsigned hxA = dx ? hxA1 : hxA0;
                unsigned hxB = dx ? hxB1 : hxB0;
                #pragma unroll
                for (int dy = 0; dy < 2; dy++) {
                    unsigned hxyA = hxA ^ (dy ? hyA1 : hyA0);
                    unsigned hxyB = hxB ^ (dy ? hyB1 : hyB0);
                    #pragma unroll
                    for (int dz = 0; dz < 2; dz++) {
                        unsigned idxA = (hxyA ^ (dz ? hzA1 : hzA0)) & mask;
                        unsigned idxB = (hxyB ^ (dz ? hzB1 : hzB0)) & mask;
                        unsigned long long tA = __ldg(tab8 + idxA);
                        unsigned long long tB = __ldg(tab8 + idxB);
                        float wA = wxdA * (dy ? (dz ? A.wyz11 : A.wyz10)
                                              : (dz ? A.wyz01 : A.wyz00));
                        float wB = wxdB * (dy ? (dz ? B.wyz11 : B.wyz10)
                                              : (dz ? B.wyz01 : B.wyz00));
                        ffma2(aA, pack2(wA, wA), tA);
                        ffma2(aB, pack2(wB, wB), tB);
                    }
                }
            }
        }
        fA[l] = aA;
        fB[l] = aB;
    }

    // ---- fused MLP for both items: w1 from the constant port (off l1tex) ----
    unsigned long long accA01 = 0ull, accA23 = 0ull, accA45 = 0ull, accA67 = 0ull;
    unsigned long long accB01 = 0ull, accB23 = 0ull, accB45 = 0ull, accB67 = 0ull;

    #pragma unroll 2
    for (int j = 0; j < 64; j++) {
        unsigned long long hA0 = 0ull, hA1 = 0ull, hB0 = 0ull, hB1 = 0ull;
        #pragma unroll
        for (int q = 0; q < 8; q++) {
            ulonglong2 wv = c_w1t[j * 8 + q];
            ffma2(hA0, fA[2 * q],     wv.x);
            ffma2(hA1, fA[2 * q + 1], wv.y);
            ffma2(hB0, fB[2 * q],     wv.x);
            ffma2(hB1, fB[2 * q + 1], wv.y);
        }
        float a0, a1, a2, a3, b0, b1, b2, b3;
        unpack2(hA0, a0, a1); unpack2(hA1, a2, a3);
        unpack2(hB0, b0, b1); unpack2(hB1, b2, b3);
        float hA = fmaxf((a0 + a1) + (a2 + a3), 0.0f) * wtA;
        float hB = fmaxf((b0 + b1) + (b2 + b3), 0.0f) * wtB;
        unsigned long long hhA = pack2(hA, hA);
        unsigned long long hhB = pack2(hB, hB);

        const ulonglong2* w2r = reinterpret_cast<const ulonglong2*>(&w2s[j][0]);
        ulonglong2 wa = w2r[0];
        ulonglong2 wb = w2r[1];
        ffma2(accA01, hhA, wa.x); ffma2(accA23, hhA, wa.y);
        ffma2(accA45, hhA, wb.x); ffma2(accA67, hhA, wb.y);
        ffma2(accB01, hhB, wa.x); ffma2(accB23, hhB, wa.y);
        ffma2(accB45, hhB, wb.x); ffma2(accB67, hhB, wb.y);
    }

    float accA[8], accB[8];
    unpack2(accA01, accA[0], accA[1]); unpack2(accA23, accA[2], accA[3]);
    unpack2(accA45, accA[4], accA[5]); unpack2(accA67, accA[6], accA[7]);
    unpack2(accB01, accB[0], accB[1]); unpack2(accB23, accB[2], accB[3]);
    unpack2(accB45, accB[4], accB[5]); unpack2(accB67, accB[6], accB[7]);

    // ---- reduce the 8 outer-corner contributions across the 8-lane group ----
    #pragma unroll
    for (int k = 0; k < 8; k++) {
        accA[k] += __shfl_xor_sync(0xffffffffu, accA[k], 1);
        accA[k] += __shfl_xor_sync(0xffffffffu, accA[k], 2);
        accA[k] += __shfl_xor_sync(0xffffffffu, accA[k], 4);
        accB[k] += __shfl_xor_sync(0xffffffffu, accB[k], 1);
        accB[k] += __shfl_xor_sync(0xffffffffu, accB[k], 2);
        accB[k] += __shfl_xor_sync(0xffffffffu, accB[k], 4);
    }
    // lane oc writes output element oc of its point -> coalesced stores
    float tA0 = (oc & 1) ? accA[1] : accA[0];
    float tA1 = (oc & 1) ? accA[3] : accA[2];
    float tA2 = (oc & 1) ? accA[5] : accA[4];
    float tA3 = (oc & 1) ? accA[7] : accA[6];
    float uA0 = (oc & 2) ? tA1 : tA0;
    float uA1 = (oc & 2) ? tA3 : tA2;
    out[gtA] = (oc & 4) ? uA1 : uA0;

    float tB0 = (oc & 1) ? accB[1] : accB[0];
    float tB1 = (oc & 1) ? accB[3] : accB[2];
    float tB2 = (oc & 1) ? accB[5] : accB[4];
    float tB3 = (oc & 1) ? accB[7] : accB[6];
    float uB0 = (oc & 2) ? tB1 : tB0;
    float uB1 = (oc & 2) ? tB3 : tB2;
    out[gtB] = (oc & 4) ? uB1 : uB0;
}

extern "C" void kernel_launch(void* const* d_in, const int* in_sizes, int n_in,
                              void* d_out, int out_size)
{
    const float* xyz   = (const float*)d_in[0];
    const float* bound = (const float*)d_in[1];
    const float* table = (const float*)d_in[2];
    const float* w1    = (const float*)d_in[3];
    const float* w2    = (const float*)d_in[4];
    float* out = (float*)d_out;

    int N = in_sizes[0] / 3;

    // Stage 1: transpose w1 into device scratch, then copy into __constant__.
    transpose_w1_kernel<<<8, 256>>>(w1);
    void* w1t_ptr = nullptr;
    cudaGetSymbolAddress(&w1t_ptr, g_w1t);
    cudaMemcpyToSymbolAsync(c_w1t, w1t_ptr, 2048 * sizeof(float), 0,
                            cudaMemcpyDeviceToDevice, 0);

    // Replicate torch-ngp level construction with the exact numpy double math.
    LevelParams lev;
    double scale = exp2(log2(513.0 / 16.0) / 15.0);
    long long off = 0;
    for (int i = 0; i < NLEV; i++) {
        int res = (int)ceil(16.0 * pow(scale, (double)i));
        long long cube = (long long)(res + 1) * (res + 1) * (res + 1);
        long long n = cube;
        if (n > (1LL << 19)) n = (1LL << 19);
        n = ((n + 7) / 8) * 8;
        lev.R[i] = res;
        lev.H[i] = (unsigned)n;
        lev.O[i] = (int)off;
        lev.linear[i] = (cube <= n) ? 1 : 0;
        off += n;
    }

    int half = (N * 8) / 2;
    int blocks = (half + 127) / 128;
    grid_fused_kernel<<<blocks, 128>>>(xyz, bound, table, w2, out, lev, N);
}

// round 6
// speedup vs baseline: 1.5719x; 1.0537x over previous
#include <cuda_runtime.h>
#include <math.h>

#define NLEV 16
#define P2 2654435761u
#define P3 805459861u

struct LevelParams {
    int          R[NLEV];
    unsigned int H[NLEV];
    int          O[NLEV];
    int          linear[NLEV];
};

// w1 transposed: entry [j*8+q] = {w1[4q][j], w1[4q+1][j], w1[4q+2][j], w1[4q+3][j]}.
// Kept in BOTH constant memory and shared memory; the MLP loop alternates the
// source per hidden unit j so the const port and the smem crossbar each carry
// half the weight traffic concurrently.
__constant__ __align__(16) ulonglong2 c_w1t[512];
__device__   __align__(16) float      g_w1t[2048];   // transpose scratch (also smem source)

__device__ __forceinline__ unsigned long long pack2(float lo, float hi) {
    unsigned long long r;
    asm("mov.b64 %0, {%1, %2};" : "=l"(r) : "f"(lo), "f"(hi));
    return r;
}
__device__ __forceinline__ void unpack2(unsigned long long v, float &lo, float &hi) {
    asm("mov.b64 {%0, %1}, %2;" : "=f"(lo), "=f"(hi) : "l"(v));
}
// d += a * b elementwise on packed f32x2 (exact fp32 semantics, 2 FMAs / slot)
__device__ __forceinline__ void ffma2(unsigned long long &d, unsigned long long a, unsigned long long b) {
    asm("fma.rn.f32x2 %0, %1, %2, %0;" : "+l"(d) : "l"(a), "l"(b));
}

__global__ void transpose_w1_kernel(const float* __restrict__ w1) {
    int i = blockIdx.x * 256 + threadIdx.x;      // i over 2048 entries
    if (i < 2048) {
        int j = i >> 5;          // hidden unit 0..63
        int r = i & 31;          // input 0..31
        g_w1t[j * 32 + r] = w1[r * 64 + j];      // w1 is [32,64] row-major
    }
}

// Computes (ex,ey,ez, wt) for item (point p, outer corner oc).
__device__ __forceinline__ void setup_item(
    const float* __restrict__ xyz, float b, float inv2b, int p, int oc,
    float& ex, float& ey, float& ez, float& wt)
{
    float cx = (xyz[3 * p + 0] + b) * inv2b * 512.0f;
    float cy = (xyz[3 * p + 1] + b) * inv2b * 512.0f;
    float cz = (xyz[3 * p + 2] + b) * inv2b * 512.0f;

    int c0x = min(max((int)floorf(cx), 0), 511);
    int c0y = min(max((int)floorf(cy), 0), 511);
    int c0z = min(max((int)floorf(cz), 0), 511);

    float u = cx - (float)c0x;
    float v = cy - (float)c0y;
    float w = cz - (float)c0z;

    int ox = (oc >> 2) & 1, oy = (oc >> 1) & 1, oz = oc & 1;
    wt = (ox ? u : 1.0f - u) * (oy ? v : 1.0f - v) * (oz ? w : 1.0f - w);

    ex = (float)(c0x + ox) * (1.0f / 512.0f);
    ey = (float)(c0y + oy) * (1.0f / 512.0f);
    ez = (float)(c0z + oz) * (1.0f / 512.0f);
}

// Per-level interp weights + integer cell for one encode-point.
struct LevWts {
    float wx0, fx;
    float wyz00, wyz01, wyz10, wyz11;
    int ix, iy, iz;
};

__device__ __forceinline__ LevWts level_setup(float Rf, float ex, float ey, float ez) {
    LevWts s;
    float px = ex * Rf + 0.5f;   // ex*R exact (k*R < 2^24) -> rounding-free
    float py = ey * Rf + 0.5f;
    float pz = ez * Rf + 0.5f;
    float pgx = floorf(px), pgy = floorf(py), pgz = floorf(pz);
    float fx = px - pgx, fy = py - pgy, fz = pz - pgz;
    s.ix = (int)pgx; s.iy = (int)pgy; s.iz = (int)pgz;
    s.fx = fx; s.wx0 = 1.0f - fx;
    float wy0 = 1.0f - fy, wz0 = 1.0f - fz;
    s.wyz00 = wy0 * wz0; s.wyz01 = wy0 * fz; s.wyz10 = fy * wz0; s.wyz11 = fy * fz;
    return s;
}

__global__ void __launch_bounds__(128, 4) grid_fused_kernel(
    const float* __restrict__ xyz,
    const float* __restrict__ bound,
    const float* __restrict__ table,
    const float* __restrict__ w2,
    float* __restrict__ out,
    LevelParams lev, int N)
{
    __shared__ __align__(16) ulonglong2 w1sh[512];   // same layout as c_w1t
    __shared__ __align__(16) float      w2s[64][8];

    const int tid = threadIdx.x;
    {
        const ulonglong2* src = reinterpret_cast<const ulonglong2*>(g_w1t);
        for (int i = tid; i < 512; i += 128) w1sh[i] = src[i];
        for (int i = tid; i < 64 * 8; i += 128) w2s[i >> 3][i & 7] = w2[i];
    }
    __syncthreads();

    const int M     = N * 8;                     // total (point, corner) items
    const int half  = M >> 1;
    int T = blockIdx.x * 128 + tid;              // thread handles items T and T+half
    if (T >= half) return;

    int gtA = T;
    int gtB = T + half;
    int pA  = gtA >> 3;
    int pB  = gtB >> 3;
    int oc  = gtA & 7;    // same for both items (half is a multiple of 8)

    const float b     = bound[0];
    const float inv2b = 1.0f / (2.0f * b);

    float exA, eyA, ezA, wtA;
    float exB, eyB, ezB, wtB;
    setup_item(xyz, b, inv2b, pA, oc, exA, eyA, ezA, wtA);
    setup_item(xyz, b, inv2b, pB, oc, exB, eyB, ezB, wtB);

    unsigned long long fA[NLEV], fB[NLEV];

    // ---- interleaved encode: both items per level -> 16 independent gathers in flight ----
    #pragma unroll
    for (int l = 0; l < NLEV; l++) {
        const float Rf = (float)lev.R[l];
        const unsigned H = lev.H[l];
        const unsigned long long* tab8 =
            reinterpret_cast<const unsigned long long*>(table) + lev.O[l];

        LevWts A = level_setup(Rf, exA, eyA, ezA);
        LevWts B = level_setup(Rf, exB, eyB, ezB);

        unsigned long long aA = 0ull, aB = 0ull;

        if (lev.linear[l]) {
            int s1 = lev.R[l] + 1, s2 = s1 * s1;
            int baseA = A.ix + A.iy * s1 + A.iz * s2;
            int baseB = B.ix + B.iy * s1 + B.iz * s2;
            #pragma unroll
            for (int dx = 0; dx < 2; dx++) {
                float wxdA = dx ? A.fx : A.wx0;
                float wxdB = dx ? B.fx : B.wx0;
                #pragma unroll
                for (int dy = 0; dy < 2; dy++) {
                    #pragma unroll
                    for (int dz = 0; dz < 2; dz++) {
                        int idxA = baseA + dx + dy * s1 + dz * s2;
                        int idxB = baseB + dx + dy * s1 + dz * s2;
                        if (idxA >= (int)H) idxA -= (int)H;   // idx < 2H provable
                        if (idxB >= (int)H) idxB -= (int)H;
                        unsigned long long tA = __ldg(tab8 + idxA);
                        unsigned long long tB = __ldg(tab8 + idxB);
                        float wA = wxdA * (dy ? (dz ? A.wyz11 : A.wyz10)
                                              : (dz ? A.wyz01 : A.wyz00));
                        float wB = wxdB * (dy ? (dz ? B.wyz11 : B.wyz10)
                                              : (dz ? B.wyz01 : B.wyz00));
                        ffma2(aA, pack2(wA, wA), tA);
                        ffma2(aB, pack2(wB, wB), tB);
                    }
                }
            }
        } else {
            unsigned mask = H - 1u;                 // H == 2^19 for hashed levels
            unsigned hxA0 = (unsigned)A.ix,      hxA1 = hxA0 + 1u;
            unsigned hyA0 = (unsigned)A.iy * P2, hyA1 = hyA0 + P2;
            unsigned hzA0 = (unsigned)A.iz * P3, hzA1 = hzA0 + P3;
            unsigned hxB0 = (unsigned)B.ix,      hxB1 = hxB0 + 1u;
            unsigned hyB0 = (unsigned)B.iy * P2, hyB1 = hyB0 + P2;
            unsigned hzB0 = (unsigned)B.iz * P3, hzB1 = hzB0 + P3;
            #pragma unroll
            for (int dx = 0; dx < 2; dx++) {
                float wxdA = dx ? A.fx : A.wx0;
                float wxdB = dx ? B.fx : B.wx0;
                unsigned hxA = dx ? hxA1 : hxA0;
                unsigned hxB = dx ? hxB1 : hxB0;
                #pragma unroll
                for (int dy = 0; dy < 2; dy++) {
                    unsigned hxyA = hxA ^ (dy ? hyA1 : hyA0);
                    unsigned hxyB = hxB ^ (dy ? hyB1 : hyB0);
                    #pragma unroll
                    for (int dz = 0; dz < 2; dz++) {
                        unsigned idxA = (hxyA ^ (dz ? hzA1 : hzA0)) & mask;
                        unsigned idxB = (hxyB ^ (dz ? hzB1 : hzB0)) & mask;
                        unsigned long long tA = __ldg(tab8 + idxA);
                        unsigned long long tB = __ldg(tab8 + idxB);
                        float wA = wxdA * (dy ? (dz ? A.wyz11 : A.wyz10)
                                              : (dz ? A.wyz01 : A.wyz00));
                        float wB = wxdB * (dy ? (dz ? B.wyz11 : B.wyz10)
                                              : (dz ? B.wyz01 : B.wyz00));
                        ffma2(aA, pack2(wA, wA), tA);
                        ffma2(aB, pack2(wB, wB), tB);
                    }
                }
            }
        }
        fA[l] = aA;
        fB[l] = aB;
    }

    // ---- fused MLP: alternate w1 source (const port / smem crossbar) per j ----
    unsigned long long accA01 = 0ull, accA23 = 0ull, accA45 = 0ull, accA67 = 0ull;
    unsigned long long accB01 = 0ull, accB23 = 0ull, accB45 = 0ull, accB67 = 0ull;

    #pragma unroll 4
    for (int j = 0; j < 64; j++) {
        unsigned long long hA0 = 0ull, hA1 = 0ull, hB0 = 0ull, hB1 = 0ull;
        if (j & 1) {
            #pragma unroll
            for (int q = 0; q < 8; q++) {
                ulonglong2 wv = w1sh[j * 8 + q];          // smem crossbar (broadcast)
                ffma2(hA0, fA[2 * q],     wv.x);
                ffma2(hA1, fA[2 * q + 1], wv.y);
                ffma2(hB0, fB[2 * q],     wv.x);
                ffma2(hB1, fB[2 * q + 1], wv.y);
            }
        } else {
            #pragma unroll
            for (int q = 0; q < 8; q++) {
                ulonglong2 wv = c_w1t[j * 8 + q];          // constant port
                ffma2(hA0, fA[2 * q],     wv.x);
                ffma2(hA1, fA[2 * q + 1], wv.y);
                ffma2(hB0, fB[2 * q],     wv.x);
                ffma2(hB1, fB[2 * q + 1], wv.y);
            }
        }
        float a0, a1, a2, a3, b0, b1, b2, b3;
        unpack2(hA0, a0, a1); unpack2(hA1, a2, a3);
        unpack2(hB0, b0, b1); unpack2(hB1, b2, b3);
        float hA = fmaxf((a0 + a1) + (a2 + a3), 0.0f) * wtA;
        float hB = fmaxf((b0 + b1) + (b2 + b3), 0.0f) * wtB;
        unsigned long long hhA = pack2(hA, hA);
        unsigned long long hhB = pack2(hB, hB);

        const ulonglong2* w2r = reinterpret_cast<const ulonglong2*>(&w2s[j][0]);
        ulonglong2 wa = w2r[0];
        ulonglong2 wb = w2r[1];
        ffma2(accA01, hhA, wa.x); ffma2(accA23, hhA, wa.y);
        ffma2(accA45, hhA, wb.x); ffma2(accA67, hhA, wb.y);
        ffma2(accB01, hhB, wa.x); ffma2(accB23, hhB, wa.y);
        ffma2(accB45, hhB, wb.x); ffma2(accB67, hhB, wb.y);
    }

    float accA[8], accB[8];
    unpack2(accA01, accA[0], accA[1]); unpack2(accA23, accA[2], accA[3]);
    unpack2(accA45, accA[4], accA[5]); unpack2(accA67, accA[6], accA[7]);
    unpack2(accB01, accB[0], accB[1]); unpack2(accB23, accB[2], accB[3]);
    unpack2(accB45, accB[4], accB[5]); unpack2(accB67, accB[6], accB[7]);

    // ---- reduce the 8 outer-corner contributions across the 8-lane group ----
    #pragma unroll
    for (int k = 0; k < 8; k++) {
        accA[k] += __shfl_xor_sync(0xffffffffu, accA[k], 1);
        accA[k] += __shfl_xor_sync(0xffffffffu, accA[k], 2);
        accA[k] += __shfl_xor_sync(0xffffffffu, accA[k], 4);
        accB[k] += __shfl_xor_sync(0xffffffffu, accB[k], 1);
        accB[k] += __shfl_xor_sync(0xffffffffu, accB[k], 2);
        accB[k] += __shfl_xor_sync(0xffffffffu, accB[k], 4);
    }
    // lane oc writes output element oc of its point -> coalesced stores
    float tA0 = (oc & 1) ? accA[1] : accA[0];
    float tA1 = (oc & 1) ? accA[3] : accA[2];
    float tA2 = (oc & 1) ? accA[5] : accA[4];
    float tA3 = (oc & 1) ? accA[7] : accA[6];
    float uA0 = (oc & 2) ? tA1 : tA0;
    float uA1 = (oc & 2) ? tA3 : tA2;
    out[gtA] = (oc & 4) ? uA1 : uA0;

    float tB0 = (oc & 1) ? accB[1] : accB[0];
    float tB1 = (oc & 1) ? accB[3] : accB[2];
    float tB2 = (oc & 1) ? accB[5] : accB[4];
    float tB3 = (oc & 1) ? accB[7] : accB[6];
    float uB0 = (oc & 2) ? tB1 : tB0;
    float uB1 = (oc & 2) ? tB3 : tB2;
    out[gtB] = (oc & 4) ? uB1 : uB0;
}

extern "C" void kernel_launch(void* const* d_in, const int* in_sizes, int n_in,
                              void* d_out, int out_size)
{
    const float* xyz   = (const float*)d_in[0];
    const float* bound = (const float*)d_in[1];
    const float* table = (const float*)d_in[2];
    const float* w1    = (const float*)d_in[3];
    const float* w2    = (const float*)d_in[4];
    float* out = (float*)d_out;

    int N = in_sizes[0] / 3;

    // Stage 1: transpose w1 into device scratch, then mirror into __constant__.
    transpose_w1_kernel<<<8, 256>>>(w1);
    void* w1t_ptr = nullptr;
    cudaGetSymbolAddress(&w1t_ptr, g_w1t);
    cudaMemcpyToSymbolAsync(c_w1t, w1t_ptr, 2048 * sizeof(float), 0,
                            cudaMemcpyDeviceToDevice, 0);

    // Replicate torch-ngp level construction with the exact numpy double math.
    LevelParams lev;
    double scale = exp2(log2(513.0 / 16.0) / 15.0);
    long long off = 0;
    for (int i = 0; i < NLEV; i++) {
        int res = (int)ceil(16.0 * pow(scale, (double)i));
        long long cube = (long long)(res + 1) * (res + 1) * (res + 1);
        long long n = cube;
        if (n > (1LL << 19)) n = (1LL << 19);
        n = ((n + 7) / 8) * 8;
        lev.R[i] = res;
        lev.H[i] = (unsigned)n;
        lev.O[i] = (int)off;
        lev.linear[i] = (cube <= n) ? 1 : 0;
        off += n;
    }

    int half = (N * 8) / 2;
    int blocks = (half + 127) / 128;
    grid_fused_kernel<<<blocks, 128>>>(xyz, bound, table, w2, out, lev, N);
}

// round 8
// speedup vs baseline: 1.7158x; 1.0916x over previous
#include <cuda_runtime.h>
#include <cuda_bf16.h>
#include <math.h>
#include <stdint.h>

#define NLEV 16
#define P2 2654435761u
#define P3 805459861u

struct LevelParams {
    int          R[NLEV];
    unsigned int H[NLEV];
    int          O[NLEV];
    int          linear[NLEV];
};

// Prepared weight tile images (global scratch; staged to smem per CTA).
// g_w1b: row j (0..63) x 32 u32. m<16: bf16-hi pairs of w1[2m][j],w1[2m+1][j]; m>=16: bf16-lo pairs.
// g_w2b: row (0..15) x 32 u32. rows 0..7: hi pairs of w2t[ok][2m..2m+1]; rows 8..15: lo pairs.
__device__ __align__(16) unsigned g_w1b[2048];
__device__ __align__(16) unsigned g_w2b[512];

// smem layout (static): A tile 256x128B, w1 tile 64x128B, w2 tile 16x128B
#define SMEM_A   0
#define SMEM_W1  32768
#define SMEM_W2  40960
#define SMEM_TOT 43008

#define SW128(o) ((o) ^ (((o) >> 3) & 0x70))

// ---------------- helpers ----------------
__device__ __forceinline__ uint32_t smem_to_u32(const void* p) {
    uint32_t a;
    asm("{ .reg .u64 t; cvta.to.shared.u64 t, %1; cvt.u32.u64 %0, t; }" : "=r"(a) : "l"(p));
    return a;
}
__device__ __forceinline__ unsigned long long pack2(float lo, float hi) {
    unsigned long long r;
    asm("mov.b64 %0, {%1, %2};" : "=l"(r) : "f"(lo), "f"(hi));
    return r;
}
__device__ __forceinline__ void unpack2(unsigned long long v, float &lo, float &hi) {
    asm("mov.b64 {%0, %1}, %2;" : "=f"(lo), "=f"(hi) : "l"(v));
}
__device__ __forceinline__ void ffma2(unsigned long long &d, unsigned long long a, unsigned long long b) {
    asm("fma.rn.f32x2 %0, %1, %2, %0;" : "+l"(d) : "l"(a), "l"(b));
}
__device__ __forceinline__ unsigned packbf(__nv_bfloat16 a, __nv_bfloat16 b) {
    __nv_bfloat162 t = __halves2bfloat162(a, b);   // lo16=a, hi16=b
    unsigned r; memcpy(&r, &t, 4); return r;
}
// pack two f32 into bf16x2: lo16 = cvt(lo), hi16 = cvt(hi)
__device__ __forceinline__ unsigned cvt_pack_bf(float lo, float hi) {
    unsigned r;
    asm("cvt.rn.bf16x2.f32 %0, %1, %2;" : "=r"(r) : "f"(hi), "f"(lo));
    return r;
}
__device__ __forceinline__ float bflo_f(unsigned u) { return __uint_as_float(u << 16); }
__device__ __forceinline__ float bfhi_f(unsigned u) { return __uint_as_float(u & 0xffff0000u); }

__device__ __forceinline__ void ldsm_x4(unsigned& r0, unsigned& r1, unsigned& r2, unsigned& r3, uint32_t a) {
    asm volatile("ldmatrix.sync.aligned.m8n8.x4.shared.b16 {%0,%1,%2,%3}, [%4];"
        : "=r"(r0), "=r"(r1), "=r"(r2), "=r"(r3) : "r"(a));
}
__device__ __forceinline__ void ldsm_x2(unsigned& r0, unsigned& r1, uint32_t a) {
    asm volatile("ldmatrix.sync.aligned.m8n8.x2.shared.b16 {%0,%1}, [%2];"
        : "=r"(r0), "=r"(r1) : "r"(a));
}
__device__ __forceinline__ void mma_bf16(float* d, const unsigned* a, const unsigned* b) {
    asm volatile("mma.sync.aligned.m16n8k16.row.col.f32.bf16.bf16.f32 "
        "{%0,%1,%2,%3}, {%4,%5,%6,%7}, {%8,%9}, {%0,%1,%2,%3};"
        : "+f"(d[0]), "+f"(d[1]), "+f"(d[2]), "+f"(d[3])
        : "r"(a[0]), "r"(a[1]), "r"(a[2]), "r"(a[3]), "r"(b[0]), "r"(b[1]));
}

// ---------------- prep kernels ----------------
__global__ void prep_w1_kernel(const float* __restrict__ w1) {
    int i = blockIdx.x * 256 + threadIdx.x;
    if (i >= 2048) return;
    int j = i >> 5, m = i & 31;
    int k = (m & 15) * 2;
    float v0 = w1[k * 64 + j];              // w1 is [32,64] row-major
    float v1 = w1[(k + 1) * 64 + j];
    __nv_bfloat16 h0 = __float2bfloat16(v0), h1 = __float2bfloat16(v1);
    unsigned r;
    if (m < 16) r = packbf(h0, h1);
    else r = packbf(__float2bfloat16(v0 - __bfloat162float(h0)),
                    __float2bfloat16(v1 - __bfloat162float(h1)));
    g_w1b[j * 32 + m] = r;
}
__global__ void prep_w2_kernel(const float* __restrict__ w2) {
    int i = blockIdx.x * 256 + threadIdx.x;
    if (i >= 512) return;
    int row = i >> 5, m = i & 31;
    int ok = row & 7, term = row >> 3;
    float v0 = w2[(2 * m) * 8 + ok];        // w2 is [64,8] row-major
    float v1 = w2[(2 * m + 1) * 8 + ok];
    __nv_bfloat16 h0 = __float2bfloat16(v0), h1 = __float2bfloat16(v1);
    unsigned r;
    if (!term) r = packbf(h0, h1);
    else r = packbf(__float2bfloat16(v0 - __bfloat162float(h0)),
                    __float2bfloat16(v1 - __bfloat162float(h1)));
    g_w2b[row * 32 + m] = r;
}

// ---------------- encode helpers (proven from R6) ----------------
__device__ __forceinline__ void setup_item(
    const float* __restrict__ xyz, float b, float inv2b, int p, int oc,
    float& ex, float& ey, float& ez, float& wt)
{
    float cx = (xyz[3 * p + 0] + b) * inv2b * 512.0f;
    float cy = (xyz[3 * p + 1] + b) * inv2b * 512.0f;
    float cz = (xyz[3 * p + 2] + b) * inv2b * 512.0f;
    int c0x = min(max((int)floorf(cx), 0), 511);
    int c0y = min(max((int)floorf(cy), 0), 511);
    int c0z = min(max((int)floorf(cz), 0), 511);
    float u = cx - (float)c0x, v = cy - (float)c0y, w = cz - (float)c0z;
    int ox = (oc >> 2) & 1, oy = (oc >> 1) & 1, oz = oc & 1;
    wt = (ox ? u : 1.0f - u) * (oy ? v : 1.0f - v) * (oz ? w : 1.0f - w);
    ex = (float)(c0x + ox) * (1.0f / 512.0f);
    ey = (float)(c0y + oy) * (1.0f / 512.0f);
    ez = (float)(c0z + oz) * (1.0f / 512.0f);
}
struct LevWts {
    float wx0, fx;
    float wyz00, wyz01, wyz10, wyz11;
    int ix, iy, iz;
};
__device__ __forceinline__ LevWts level_setup(float Rf, float ex, float ey, float ez) {
    LevWts s;
    float px = ex * Rf + 0.5f, py = ey * Rf + 0.5f, pz = ez * Rf + 0.5f;
    float pgx = floorf(px), pgy = floorf(py), pgz = floorf(pz);
    float fx = px - pgx, fy = py - pgy, fz = pz - pgz;
    s.ix = (int)pgx; s.iy = (int)pgy; s.iz = (int)pgz;
    s.fx = fx; s.wx0 = 1.0f - fx;
    float wy0 = 1.0f - fy, wz0 = 1.0f - fz;
    s.wyz00 = wy0 * wz0; s.wyz01 = wy0 * fz; s.wyz10 = fy * wz0; s.wyz11 = fy * fz;
    return s;
}
// split feature row to bf16 hi(bytes 0..63)/lo(64..127) in the SW128 A tile
__device__ __forceinline__ void store_feat_row(char* smem, int row,
                                               const unsigned long long* f2)
{
    unsigned hi[16], lo[16];
    #pragma unroll
    for (int l = 0; l < 16; l++) {
        float f0, f1; unpack2(f2[l], f0, f1);
        __nv_bfloat16 h0 = __float2bfloat16(f0);
        __nv_bfloat16 h1 = __float2bfloat16(f1);
        hi[l] = packbf(h0, h1);
        lo[l] = packbf(__float2bfloat16(f0 - __bfloat162float(h0)),
                       __float2bfloat16(f1 - __bfloat162float(h1)));
    }
    #pragma unroll
    for (int q = 0; q < 4; q++) {
        uint32_t offh = SW128(row * 128 + q * 16);
        *reinterpret_cast<uint4*>(smem + SMEM_A + offh) =
            make_uint4(hi[4*q], hi[4*q+1], hi[4*q+2], hi[4*q+3]);
        uint32_t offl = SW128(row * 128 + 64 + q * 16);
        *reinterpret_cast<uint4*>(smem + SMEM_A + offl) =
            make_uint4(lo[4*q], lo[4*q+1], lo[4*q+2], lo[4*q+3]);
    }
}

// ---------------- main kernel ----------------
__global__ void __launch_bounds__(128, 4) grid_fused_kernel(
    const float* __restrict__ xyz,
    const float* __restrict__ bound,
    const float* __restrict__ table,
    float* __restrict__ out,
    LevelParams lev, int N)
{
    __shared__ __align__(1024) char smem[SMEM_TOT];
    const uint32_t sb = smem_to_u32(smem);
    const int tid = threadIdx.x;
    const int wid = tid >> 5;
    const int ln  = tid & 31;

    // stage weight tiles (swizzled)
    for (int i = tid; i < 2048; i += 128) {
        int row = i >> 5, m = i & 31;
        *reinterpret_cast<unsigned*>(smem + SMEM_W1 + SW128(row * 128 + m * 4)) = g_w1b[i];
    }
    for (int i = tid; i < 512; i += 128) {
        int row = i >> 5, m = i & 31;
        *reinterpret_cast<unsigned*>(smem + SMEM_W2 + SW128(row * 128 + m * 4)) = g_w2b[i];
    }
    __syncthreads();

    const int half = (N * 8) >> 1;
    int T = blockIdx.x * 128 + tid;          // exact fit: N*8/2 == 8192*128
    int gtA = T, gtB = T + half;
    int pA = gtA >> 3, pB = gtB >> 3;
    int oc = gtA & 7;

    const float b     = bound[0];
    const float inv2b = 1.0f / (2.0f * b);

    float exA, eyA, ezA, wtA, exB, eyB, ezB, wtB;
    setup_item(xyz, b, inv2b, pA, oc, exA, eyA, ezA, wtA);
    setup_item(xyz, b, inv2b, pB, oc, exB, eyB, ezB, wtB);

    unsigned long long fA[NLEV], fB[NLEV];

    // ---- interleaved hash-grid encode (proven R6 path) ----
    #pragma unroll
    for (int l = 0; l < NLEV; l++) {
        const float Rf = (float)lev.R[l];
        const unsigned H = lev.H[l];
        const unsigned long long* tab8 =
            reinterpret_cast<const unsigned long long*>(table) + lev.O[l];
        LevWts A = level_setup(Rf, exA, eyA, ezA);
        LevWts B = level_setup(Rf, exB, eyB, ezB);
        unsigned long long aA = 0ull, aB = 0ull;
        if (lev.linear[l]) {
            int s1 = lev.R[l] + 1, s2 = s1 * s1;
            int baseA = A.ix + A.iy * s1 + A.iz * s2;
            int baseB = B.ix + B.iy * s1 + B.iz * s2;
            #pragma unroll
            for (int dx = 0; dx < 2; dx++) {
                float wxdA = dx ? A.fx : A.wx0;
                float wxdB = dx ? B.fx : B.wx0;
                #pragma unroll
                for (int dy = 0; dy < 2; dy++) {
                    #pragma unroll
                    for (int dz = 0; dz < 2; dz++) {
                        int idxA = baseA + dx + dy * s1 + dz * s2;
                        int idxB = baseB + dx + dy * s1 + dz * s2;
                        if (idxA >= (int)H) idxA -= (int)H;
                        if (idxB >= (int)H) idxB -= (int)H;
                        unsigned long long tA = __ldg(tab8 + idxA);
                        unsigned long long tB = __ldg(tab8 + idxB);
                        float wA = wxdA * (dy ? (dz ? A.wyz11 : A.wyz10)
                                              : (dz ? A.wyz01 : A.wyz00));
                        float wB = wxdB * (dy ? (dz ? B.wyz11 : B.wyz10)
                                              : (dz ? B.wyz01 : B.wyz00));
                        ffma2(aA, pack2(wA, wA), tA);
                        ffma2(aB, pack2(wB, wB), tB);
                    }
                }
            }
        } else {
            unsigned mask = H - 1u;
            unsigned hxA0 = (unsigned)A.ix,      hxA1 = hxA0 + 1u;
            unsigned hyA0 = (unsigned)A.iy * P2, hyA1 = hyA0 + P2;
            unsigned hzA0 = (unsigned)A.iz * P3, hzA1 = hzA0 + P3;
            unsigned hxB0 = (unsigned)B.ix,      hxB1 = hxB0 + 1u;
            unsigned hyB0 = (unsigned)B.iy * P2, hyB1 = hyB0 + P2;
            unsigned hzB0 = (unsigned)B.iz * P3, hzB1 = hzB0 + P3;
            #pragma unroll
            for (int dx = 0; dx < 2; dx++) {
                float wxdA = dx ? A.fx : A.wx0;
                float wxdB = dx ? B.fx : B.wx0;
                unsigned hxA = dx ? hxA1 : hxA0;
                unsigned hxB = dx ? hxB1 : hxB0;
                #pragma unroll
                for (int dy = 0; dy < 2; dy++) {
                    unsigned hxyA = hxA ^ (dy ? hyA1 : hyA0);
                    unsigned hxyB = hxB ^ (dy ? hyB1 : hyB0);
                    #pragma unroll
                    for (int dz = 0; dz < 2; dz++) {
                        unsigned idxA = (hxyA ^ (dz ? hzA1 : hzA0)) & mask;
                        unsigned idxB = (hxyB ^ (dz ? hzB1 : hzB0)) & mask;
                        unsigned long long tA = __ldg(tab8 + idxA);
                        unsigned long long tB = __ldg(tab8 + idxB);
                        float wA = wxdA * (dy ? (dz ? A.wyz11 : A.wyz10)
                                              : (dz ? A.wyz01 : A.wyz00));
                        float wB = wxdB * (dy ? (dz ? B.wyz11 : B.wyz10)
                                              : (dz ? B.wyz01 : B.wyz00));
                        ffma2(aA, pack2(wA, wA), tA);
                        ffma2(aB, pack2(wB, wB), tB);
                    }
                }
            }
        }
        fA[l] = aA;
        fB[l] = aB;
    }

    // feats -> smem A tile (warp-private rows; item A -> 64w+ln, item B -> 64w+32+ln)
    store_feat_row(smem, wid * 64 + ln,      fA);
    store_feat_row(smem, wid * 64 + 32 + ln, fB);
    __syncwarp();

    // ---- load w1 B-fragments once: b1[nt][term][kst][reg] ----
    unsigned b1[8][2][2][2];
    #pragma unroll
    for (int nt = 0; nt < 8; nt++) {
        #pragma unroll
        for (int term = 0; term < 2; term++) {
            uint32_t row  = nt * 8 + (ln & 7);
            uint32_t byte = term * 64 + (ln >> 3) * 16;
            uint32_t ad = sb + SMEM_W1 + SW128(row * 128 + byte);
            ldsm_x4(b1[nt][term][0][0], b1[nt][term][0][1],
                    b1[nt][term][1][0], b1[nt][term][1][1], ad);
        }
    }

    const int baseAI = blockIdx.x * 128 + wid * 32;   // global item idx of warp row 0

    #pragma unroll
    for (int t = 0; t < 4; t++) {
        // A1 fragments for this mtile (hi/lo x 2 ksteps)
        unsigned ahi[2][4], alo[2][4];
        #pragma unroll
        for (int s = 0; s < 2; s++) {
            #pragma unroll
            for (int term = 0; term < 2; term++) {
                int mat = ln >> 3;
                uint32_t row  = wid * 64 + t * 16 + (mat & 1) * 8 + (ln & 7);
                uint32_t byte = term * 64 + s * 32 + (mat >> 1) * 16;
                uint32_t ad = sb + SMEM_A + SW128(row * 128 + byte);
                if (term) ldsm_x4(alo[s][0], alo[s][1], alo[s][2], alo[s][3], ad);
                else      ldsm_x4(ahi[s][0], ahi[s][1], ahi[s][2], ahi[s][3], ad);
            }
        }
        // interpolation weights for this mtile's rows (rows within half: 16*(t&1)+q)
        float wsrc = (t < 2) ? wtA : wtB;
        int tq = (t & 1) * 16;
        float wt0 = __shfl_sync(0xffffffffu, wsrc, tq + (ln >> 2));
        float wt1 = __shfl_sync(0xffffffffu, wsrc, tq + 8 + (ln >> 2));

        float D2[4] = {0.f, 0.f, 0.f, 0.f};
        #pragma unroll
        for (int s2 = 0; s2 < 4; s2++) {     // gemm2 kstep == gemm1 ntile pair
            unsigned a2hi[4], a2lo[4];
            #pragma unroll
            for (int e = 0; e < 2; e++) {
                int nt = 2 * s2 + e;
                float D1[4] = {0.f, 0.f, 0.f, 0.f};
                mma_bf16(D1, ahi[0], b1[nt][0][0]);   // hi*hi
                mma_bf16(D1, ahi[1], b1[nt][0][1]);
                mma_bf16(D1, ahi[0], b1[nt][1][0]);   // hi*lo
                mma_bf16(D1, ahi[1], b1[nt][1][1]);
                mma_bf16(D1, alo[0], b1[nt][0][0]);   // lo*hi
                mma_bf16(D1, alo[1], b1[nt][0][1]);
                float h0 = fmaxf(D1[0], 0.f) * wt0;
                float h1 = fmaxf(D1[1], 0.f) * wt0;
                float h2 = fmaxf(D1[2], 0.f) * wt1;
                float h3 = fmaxf(D1[3], 0.f) * wt1;
                unsigned p01 = cvt_pack_bf(h0, h1);
                unsigned p23 = cvt_pack_bf(h2, h3);
                a2hi[2 * e + 0] = p01;
                a2hi[2 * e + 1] = p23;
                a2lo[2 * e + 0] = cvt_pack_bf(h0 - bflo_f(p01), h1 - bfhi_f(p01));
                a2lo[2 * e + 1] = cvt_pack_bf(h2 - bflo_f(p23), h3 - bfhi_f(p23));
            }
            // w2 B-fragments for this kstep
            unsigned b2h[2], b2l[2];
            {
                int mat = (ln >> 3) & 1;
                uint32_t byte = s2 * 32 + mat * 16;
                uint32_t rowh = (ln & 7);
                ldsm_x2(b2h[0], b2h[1], sb + SMEM_W2 + SW128(rowh * 128 + byte));
                uint32_t rowl = 8 + (ln & 7);
                ldsm_x2(b2l[0], b2l[1], sb + SMEM_W2 + SW128(rowl * 128 + byte));
            }
            mma_bf16(D2, a2hi, b2h);
            mma_bf16(D2, a2hi, b2l);
            mma_bf16(D2, a2lo, b2h);
        }

        // reduce the 8 corner-rows (quads hold distinct rows; cols preserved)
        #pragma unroll
        for (int k = 0; k < 4; k++) {
            D2[k] += __shfl_xor_sync(0xffffffffu, D2[k], 4);
            D2[k] += __shfl_xor_sync(0xffffffffu, D2[k], 8);
            D2[k] += __shfl_xor_sync(0xffffffffu, D2[k], 16);
        }
        int obase = (t < 2) ? (baseAI + 16 * t) : (baseAI + half + 16 * (t - 2));
        if (ln < 4) {
            *reinterpret_cast<float2*>(out + obase + 2 * ln) = make_float2(D2[0], D2[1]);
        } else if (ln < 8) {
            *reinterpret_cast<float2*>(out + obase + 8 + 2 * (ln - 4)) = make_float2(D2[2], D2[3]);
        }
    }
}

extern "C" void kernel_launch(void* const* d_in, const int* in_sizes, int n_in,
                              void* d_out, int out_size)
{
    const float* xyz   = (const float*)d_in[0];
    const float* bound = (const float*)d_in[1];
    const float* table = (const float*)d_in[2];
    const float* w1    = (const float*)d_in[3];
    const float* w2    = (const float*)d_in[4];
    float* out = (float*)d_out;

    int N = in_sizes[0] / 3;

    prep_w1_kernel<<<8, 256>>>(w1);
    prep_w2_kernel<<<2, 256>>>(w2);

    // torch-ngp level construction (exact numpy double math)
    LevelParams lev;
    double scale = exp2(log2(513.0 / 16.0) / 15.0);
    long long off = 0;
    for (int i = 0; i < NLEV; i++) {
        int res = (int)ceil(16.0 * pow(scale, (double)i));
        long long cube = (long long)(res + 1) * (res + 1) * (res + 1);
        long long n = cube;
        if (n > (1LL << 19)) n = (1LL << 19);
        n = ((n + 7) / 8) * 8;
        lev.R[i] = res;
        lev.H[i] = (unsigned)n;
        lev.O[i] = (int)off;
        lev.linear[i] = (cube <= n) ? 1 : 0;
        off += n;
    }

    int half = (N * 8) / 2;
    int blocks = (half + 127) / 128;
    grid_fused_kernel<<<blocks, 128>>>(xyz, bound, table, out, lev, N);
}